// round 1
// baseline (speedup 1.0000x reference)
#include <cuda_runtime.h>
#include <math.h>
#include <stdint.h>

// Problem constants
#define NZ   256
#define NH   2048
#define NG   8192      // 4*NH gate rows
#define TT   256       // timesteps
#define KF4  (NH/4)    // 512 float4 per weight row
#define PBLOCK 512
#define PWARPS (PBLOCK/32)

// ---------------- device scratch (no allocations allowed) ----------------
__device__ float g_bias[4][NG];     // b_ih + b_hh per layer
__device__ float g_pre0[NG];        // z @ W_ih0^T + b0 (layer0, t=0 gates)
__device__ float g_hsA[TT * NH];    // ping-pong hidden-sequence buffers
__device__ float g_hsB[TT * NH];
__device__ unsigned g_count;        // grid barrier state (returns to 0 each barrier)
__device__ unsigned g_sense;        // parity; total barriers per launch is EVEN (1024)
                                    // so g_sense returns to 0 -> graph-replay safe

__device__ __forceinline__ float sigf(float x) { return 1.0f / (1.0f + expf(-x)); }

#define DOT4(w, v) ((w).x*(v).x + (w).y*(v).y + (w).z*(v).z + (w).w*(v).w)

// ---------------- prologue: summed biases ----------------
__global__ void bias_kernel(const float* __restrict__ bi0, const float* __restrict__ bh0,
                            const float* __restrict__ bir, const float* __restrict__ bhr) {
    int idx = blockIdx.x * blockDim.x + threadIdx.x;   // 4*NG = 32768 threads
    if (idx < 4 * NG) {
        int l = idx >> 13;          // /8192
        int r = idx & (NG - 1);
        float v = (l == 0) ? (bi0[r] + bh0[r])
                           : (bir[(size_t)(l - 1) * NG + r] + bhr[(size_t)(l - 1) * NG + r]);
        g_bias[l][r] = v;
    }
}

// ---------------- prologue: layer0 t=0 gates = z @ W_ih0^T + b0 ----------------
__global__ void pre0_kernel(const float* __restrict__ wih0, const float* __restrict__ z) {
    int gw   = (blockIdx.x * blockDim.x + threadIdx.x) >> 5;
    int lane = threadIdx.x & 31;
    int nw   = (gridDim.x * blockDim.x) >> 5;
    for (int row = gw; row < NG; row += nw) {
        const float* wr = wih0 + (size_t)row * NZ;
        float s = 0.f;
        for (int k = lane; k < NZ; k += 32) s += wr[k] * z[k];
        #pragma unroll
        for (int o = 16; o; o >>= 1) s += __shfl_xor_sync(0xffffffffu, s, o);
        if (lane == 0) g_pre0[row] = s + g_bias[0][row];
    }
}

// ---------------- grid-wide barrier (all blocks co-resident) ----------------
__device__ __forceinline__ void grid_barrier(unsigned& sense) {
    __syncthreads();
    if (threadIdx.x == 0) {
        unsigned s = sense ^ 1u;
        sense = s;
        __threadfence();   // drain this block's h writes to L2
        if (atomicAdd(&g_count, 1u) == gridDim.x - 1u) {
            g_count = 0u;
            __threadfence();
            *((volatile unsigned*)&g_sense) = s;
        } else {
            while (*((volatile unsigned*)&g_sense) != s) { /* spin on L2 line */ }
        }
        __threadfence();
    }
    __syncthreads();
}

// ---------------- main persistent LSTM kernel ----------------
// Each warp owns up to 2 hidden units (robust for gridDim>=64; one unit at grid=148).
// Cell state c lives in registers. h vectors ping-pong through g_hsA/g_hsB.
// W_ih loaded with __ldg (keep in L2), W_hh with __ldcs (evict-first stream) so the
// per-layer 67MB W_ih stays L2-resident across the 256 steps. Layer0 W_hh0 uses __ldg
// (it fits L2 entirely).
__global__ void __launch_bounds__(PBLOCK, 1)
lstm_kernel(const float* __restrict__ whh0,
            const float* __restrict__ wih_r,
            const float* __restrict__ whh_r) {
    __shared__ float4 sx[KF4];   // x_t   (prev-layer hidden at step t)
    __shared__ float4 sh[KF4];   // h_{t-1} (this layer)

    const int tid  = threadIdx.x;
    const int lane = tid & 31;
    const int widx = tid >> 5;
    const int G    = gridDim.x;
    const size_t GSTR = (size_t)NH * KF4;   // float4 stride between gate blocks

    unsigned sense = 0;

    for (int l = 0; l < 4; ++l) {
        const float* Wih = (l == 0) ? (const float*)0 : wih_r + (size_t)(l - 1) * NG * NH;
        const float* Whh = (l == 0) ? whh0 : whh_r + (size_t)(l - 1) * NG * NH;
        const float* xs  = (l == 0) ? (const float*)0 : ((l & 1) ? g_hsA : g_hsB);
        float* out       = (l & 1) ? g_hsB : g_hsA;
        const float* bias = g_bias[l];
        const bool layer0 = (l == 0);

        float cst0 = 0.f, cst1 = 0.f;   // per-warp cell states (up to 2 units)

        for (int t = 0; t < TT; ++t) {
            const bool haveX = (l > 0);
            const bool haveH = (t > 0);
            if (haveX) sx[tid] = __ldcg((const float4*)xs + (size_t)t * KF4 + tid);
            if (haveH) sh[tid] = __ldcg((const float4*)out + (size_t)(t - 1) * KF4 + tid);
            __syncthreads();

            int u = widx * G + blockIdx.x;
            #pragma unroll
            for (int rep = 0; rep < 2; ++rep, u += PWARPS * G) {
                if (u >= NH) break;
                float c = rep ? cst1 : cst0;

                float ig, fg, gg, og;
                if (layer0 && t == 0) {
                    ig = g_pre0[u];
                    fg = g_pre0[NH + u];
                    gg = g_pre0[2 * NH + u];
                    og = g_pre0[3 * NH + u];
                } else {
                    float a0 = 0.f, a1 = 0.f, a2 = 0.f, a3 = 0.f;
                    const float4* Whh4 = (const float4*)Whh + (size_t)u * KF4;
                    if (haveX && haveH) {
                        const float4* Wih4 = (const float4*)Wih + (size_t)u * KF4;
                        #pragma unroll 2
                        for (int i = lane; i < KF4; i += 32) {
                            const float4 xv = sx[i];
                            const float4 hv = sh[i];
                            float4 w;
                            w = __ldg(Wih4 + i);            a0 += DOT4(w, xv);
                            w = __ldg(Wih4 + GSTR + i);     a1 += DOT4(w, xv);
                            w = __ldg(Wih4 + 2 * GSTR + i); a2 += DOT4(w, xv);
                            w = __ldg(Wih4 + 3 * GSTR + i); a3 += DOT4(w, xv);
                            w = __ldcs(Whh4 + i);            a0 += DOT4(w, hv);
                            w = __ldcs(Whh4 + GSTR + i);     a1 += DOT4(w, hv);
                            w = __ldcs(Whh4 + 2 * GSTR + i); a2 += DOT4(w, hv);
                            w = __ldcs(Whh4 + 3 * GSTR + i); a3 += DOT4(w, hv);
                        }
                    } else if (haveH) {   // layer 0, t>0: recurrent term only (x=0)
                        #pragma unroll 2
                        for (int i = lane; i < KF4; i += 32) {
                            const float4 hv = sh[i];
                            float4 w;
                            w = __ldg(Whh4 + i);            a0 += DOT4(w, hv);
                            w = __ldg(Whh4 + GSTR + i);     a1 += DOT4(w, hv);
                            w = __ldg(Whh4 + 2 * GSTR + i); a2 += DOT4(w, hv);
                            w = __ldg(Whh4 + 3 * GSTR + i); a3 += DOT4(w, hv);
                        }
                    } else {              // l>0, t==0: h=0, input term only
                        const float4* Wih4 = (const float4*)Wih + (size_t)u * KF4;
                        #pragma unroll 2
                        for (int i = lane; i < KF4; i += 32) {
                            const float4 xv = sx[i];
                            float4 w;
                            w = __ldg(Wih4 + i);            a0 += DOT4(w, xv);
                            w = __ldg(Wih4 + GSTR + i);     a1 += DOT4(w, xv);
                            w = __ldg(Wih4 + 2 * GSTR + i); a2 += DOT4(w, xv);
                            w = __ldg(Wih4 + 3 * GSTR + i); a3 += DOT4(w, xv);
                        }
                    }
                    #pragma unroll
                    for (int o = 16; o; o >>= 1) {
                        a0 += __shfl_xor_sync(0xffffffffu, a0, o);
                        a1 += __shfl_xor_sync(0xffffffffu, a1, o);
                        a2 += __shfl_xor_sync(0xffffffffu, a2, o);
                        a3 += __shfl_xor_sync(0xffffffffu, a3, o);
                    }
                    ig = a0 + bias[u];
                    fg = a1 + bias[NH + u];
                    gg = a2 + bias[2 * NH + u];
                    og = a3 + bias[3 * NH + u];
                }

                c = sigf(fg) * c + sigf(ig) * tanhf(gg);
                float h = sigf(og) * tanhf(c);
                if (rep) cst1 = c; else cst0 = c;
                if (lane == 0) out[(size_t)t * NH + u] = h;
            }

            grid_barrier(sense);   // 256 per layer -> 1024 total (even: parity-safe)
        }
    }
}

// ---------------- epilogue: states[t] = h3[t] @ w_sp^T + b_sp ----------------
__global__ void proj_kernel(const float* __restrict__ wsp, const float* __restrict__ bsp,
                            float* __restrict__ out) {
    __shared__ float4 shh[KF4];
    const int t = blockIdx.x;
    const int tid = threadIdx.x;    // 256 threads
    const float4* h4 = (const float4*)g_hsB + (size_t)t * KF4;  // layer3 output lives in B
    shh[tid]       = h4[tid];
    shh[tid + 256] = h4[tid + 256];
    __syncthreads();
    const int widx = tid >> 5, lane = tid & 31;
    for (int o = widx; o < 64; o += 8) {
        const float4* wr = (const float4*)wsp + (size_t)o * KF4;
        float s = 0.f;
        #pragma unroll 4
        for (int i = lane; i < KF4; i += 32) {
            float4 w = __ldg(wr + i);
            float4 hv = shh[i];
            s += DOT4(w, hv);
        }
        #pragma unroll
        for (int off = 16; off; off >>= 1) s += __shfl_xor_sync(0xffffffffu, s, off);
        if (lane == 0) out[(size_t)t * 64 + o] = s + bsp[o];
    }
}

// ---------------- launch ----------------
extern "C" void kernel_launch(void* const* d_in, const int* in_sizes, int n_in,
                              void* d_out, int out_size) {
    const float* z      = (const float*)d_in[0];
    const float* w_ih0  = (const float*)d_in[1];
    const float* w_hh0  = (const float*)d_in[2];
    const float* b_ih0  = (const float*)d_in[3];
    const float* b_hh0  = (const float*)d_in[4];
    const float* w_ih_r = (const float*)d_in[5];
    const float* w_hh_r = (const float*)d_in[6];
    const float* b_ih_r = (const float*)d_in[7];
    const float* b_hh_r = (const float*)d_in[8];
    const float* w_sp   = (const float*)d_in[9];
    const float* b_sp   = (const float*)d_in[10];
    float* out = (float*)d_out;

    int dev = 0;
    cudaGetDevice(&dev);
    int sms = 0;
    cudaDeviceGetAttribute(&sms, cudaDevAttrMultiProcessorCount, dev);
    if (sms < 64) sms = 64;      // barrier needs co-residency; unit loop covers >=64
    if (sms > NH / PWARPS) {}    // fine; extra warps idle at barrier

    bias_kernel<<<64, 512>>>(b_ih0, b_hh0, b_ih_r, b_hh_r);
    pre0_kernel<<<32, 256>>>(w_ih0, z);
    lstm_kernel<<<sms, PBLOCK>>>(w_hh0, w_ih_r, w_hh_r);
    proj_kernel<<<TT, 256>>>(w_sp, b_sp, out);
}

// round 2
// speedup vs baseline: 1.4667x; 1.4667x over previous
#include <cuda_runtime.h>
#include <math.h>
#include <stdint.h>

// Problem constants
#define NZ   256
#define NH   2048
#define NG   8192      // 4*NH gate rows
#define TT   256       // timesteps
#define KF4  (NH/4)    // 512 float4 per h-vector
#define KU4  (NH/8)    // 256 uint4 (8 int16) per weight row
#define PBLOCK 512
#define PWARPS (PBLOCK/32)
#define GRID   (NH/PWARPS)   // 128 blocks: one warp per hidden unit

// ---------------- device scratch (no allocations allowed) ----------------
__device__ float g_bias[4][NG];          // b_ih + b_hh per layer
__device__ float g_pre0[NG];             // z @ W_ih0^T + b0 (layer0, t=0)
__device__ float g_hsA[TT * NH];         // ping-pong hidden-sequence buffers
__device__ float g_hsB[TT * NH];
__device__ unsigned g_count;             // grid barrier (returns to 0)
__device__ unsigned g_sense;             // parity; 1024 barriers (even) -> replay-safe

// quantized weights: biased uint16 (q = round(w/scale) + 32768)
__device__ unsigned short q_hh0[(size_t)NG * NH];       //  33.5 MB
__device__ unsigned short q_ihr[(size_t)3 * NG * NH];   // 100.7 MB
__device__ unsigned short q_hhr[(size_t)3 * NG * NH];   // 100.7 MB
__device__ float s_hh0[NG];              // per-row dequant scales
__device__ float s_ihr[3 * NG];
__device__ float s_hhr[3 * NG];

__device__ __forceinline__ float sigf(float x) { return 1.0f / (1.0f + expf(-x)); }

// biased-u16 -> float: PRMT builds 0x4B00'u16, FADD removes (2^23 + 32768)
#define CVT_LO(v) (__uint_as_float(__byte_perm((v), 0x4B000000u, 0x7410)) - 8421376.0f)
#define CVT_HI(v) (__uint_as_float(__byte_perm((v), 0x4B000000u, 0x7632)) - 8421376.0f)

// accumulate one uint4 (8 weights) against 8 h-values held in two float4s
#define ACC8(acc, w, lo, hi)                          \
    do {                                              \
        acc += CVT_LO((w).x) * (lo).x;                \
        acc += CVT_HI((w).x) * (lo).y;                \
        acc += CVT_LO((w).y) * (lo).z;                \
        acc += CVT_HI((w).y) * (lo).w;                \
        acc += CVT_LO((w).z) * (hi).x;                \
        acc += CVT_HI((w).z) * (hi).y;                \
        acc += CVT_LO((w).w) * (hi).z;                \
        acc += CVT_HI((w).w) * (hi).w;                \
    } while (0)

// ---------------- prologue: summed biases ----------------
__global__ void bias_kernel(const float* __restrict__ bi0, const float* __restrict__ bh0,
                            const float* __restrict__ bir, const float* __restrict__ bhr) {
    int idx = blockIdx.x * blockDim.x + threadIdx.x;   // 4*NG threads
    if (idx < 4 * NG) {
        int l = idx >> 13;
        int r = idx & (NG - 1);
        float v = (l == 0) ? (bi0[r] + bh0[r])
                           : (bir[(size_t)(l - 1) * NG + r] + bhr[(size_t)(l - 1) * NG + r]);
        g_bias[l][r] = v;
    }
}

// ---------------- prologue: quantize recurrent weights to biased u16 ----------------
// rows: [0,NG)       -> whh0
//       [NG,4NG)     -> wih_r (3 layers)
//       [4NG,7NG)    -> whh_r (3 layers)
__global__ void quant_kernel(const float* __restrict__ whh0,
                             const float* __restrict__ wihr,
                             const float* __restrict__ whhr) {
    int gw   = (blockIdx.x * blockDim.x + threadIdx.x) >> 5;
    int lane = threadIdx.x & 31;
    int nw   = (gridDim.x * blockDim.x) >> 5;
    for (int r = gw; r < 7 * NG; r += nw) {
        const float* src;
        unsigned short* dst;
        float* sc;
        if (r < NG) {
            src = whh0 + (size_t)r * NH; dst = q_hh0 + (size_t)r * NH; sc = &s_hh0[r];
        } else if (r < 4 * NG) {
            int rr = r - NG;
            src = wihr + (size_t)rr * NH; dst = q_ihr + (size_t)rr * NH; sc = &s_ihr[rr];
        } else {
            int rr = r - 4 * NG;
            src = whhr + (size_t)rr * NH; dst = q_hhr + (size_t)rr * NH; sc = &s_hhr[rr];
        }
        const float4* s4 = (const float4*)src;
        float m = 0.f;
        #pragma unroll 4
        for (int i = lane; i < KF4; i += 32) {
            float4 v = s4[i];
            m = fmaxf(m, fmaxf(fmaxf(fabsf(v.x), fabsf(v.y)), fmaxf(fabsf(v.z), fabsf(v.w))));
        }
        #pragma unroll
        for (int o = 16; o; o >>= 1) m = fmaxf(m, __shfl_xor_sync(0xffffffffu, m, o));
        float qs = (m > 0.f) ? 32767.0f / m : 0.f;
        if (lane == 0) *sc = (m > 0.f) ? m / 32767.0f : 0.f;
        ushort4* d4 = (ushort4*)dst;
        #pragma unroll 4
        for (int i = lane; i < KF4; i += 32) {
            float4 v = s4[i];   // L1 hit (row re-read)
            ushort4 o;
            o.x = (unsigned short)(__float2int_rn(v.x * qs) + 32768);
            o.y = (unsigned short)(__float2int_rn(v.y * qs) + 32768);
            o.z = (unsigned short)(__float2int_rn(v.z * qs) + 32768);
            o.w = (unsigned short)(__float2int_rn(v.w * qs) + 32768);
            d4[i] = o;
        }
    }
}

// ---------------- prologue: layer0 t=0 gates = z @ W_ih0^T + b0 (fp32) --------------
__global__ void pre0_kernel(const float* __restrict__ wih0, const float* __restrict__ z) {
    int gw   = (blockIdx.x * blockDim.x + threadIdx.x) >> 5;
    int lane = threadIdx.x & 31;
    int nw   = (gridDim.x * blockDim.x) >> 5;
    for (int row = gw; row < NG; row += nw) {
        const float* wr = wih0 + (size_t)row * NZ;
        float s = 0.f;
        for (int k = lane; k < NZ; k += 32) s += wr[k] * z[k];
        #pragma unroll
        for (int o = 16; o; o >>= 1) s += __shfl_xor_sync(0xffffffffu, s, o);
        if (lane == 0) g_pre0[row] = s + g_bias[0][row];
    }
}

// ---------------- grid-wide barrier ----------------
__device__ __forceinline__ void grid_barrier(unsigned& sense) {
    __syncthreads();
    if (threadIdx.x == 0) {
        unsigned s = sense ^ 1u;
        sense = s;
        __threadfence();
        if (atomicAdd(&g_count, 1u) == gridDim.x - 1u) {
            g_count = 0u;
            __threadfence();
            *((volatile unsigned*)&g_sense) = s;
        } else {
            while (*((volatile unsigned*)&g_sense) != s) { }
        }
        __threadfence();
    }
    __syncthreads();
}

// ---------------- main persistent LSTM kernel (int16 weights) ----------------
// 128 blocks x 512 threads: exactly one warp per hidden unit.
__global__ void __launch_bounds__(PBLOCK, 1)
lstm_kernel() {
    __shared__ float4 sx[KF4];   // x_t   (prev-layer hidden at step t)
    __shared__ float4 sh[KF4];   // h_{t-1} (this layer)

    const int tid  = threadIdx.x;
    const int lane = tid & 31;
    const int widx = tid >> 5;
    const int u    = blockIdx.x * PWARPS + widx;    // hidden unit, 0..2047
    const size_t GQ = (size_t)NH * KU4;             // uint4 stride between gate blocks

    unsigned sense = 0;

    for (int l = 0; l < 4; ++l) {
        const unsigned short* Wih = (l == 0) ? (const unsigned short*)0
                                             : q_ihr + (size_t)(l - 1) * NG * NH;
        const unsigned short* Whh = (l == 0) ? q_hh0
                                             : q_hhr + (size_t)(l - 1) * NG * NH;
        const float* sihs = (l == 0) ? (const float*)0 : s_ihr + (size_t)(l - 1) * NG;
        const float* shhs = (l == 0) ? s_hh0 : s_hhr + (size_t)(l - 1) * NG;
        const float* xs   = (l == 0) ? (const float*)0 : ((l & 1) ? g_hsA : g_hsB);
        float* out        = (l & 1) ? g_hsB : g_hsA;
        const float* bias = g_bias[l];
        const bool layer0 = (l == 0);

        const uint4* Wih4 = layer0 ? (const uint4*)0 : (const uint4*)Wih + (size_t)u * KU4;
        const uint4* Whh4 = (const uint4*)Whh + (size_t)u * KU4;

        float c = 0.f;   // register-resident cell state

        for (int t = 0; t < TT; ++t) {
            const bool haveX = (l > 0);
            const bool haveH = (t > 0);
            if (haveX) sx[tid] = __ldcg((const float4*)xs + (size_t)t * KF4 + tid);
            if (haveH) sh[tid] = __ldcg((const float4*)out + (size_t)(t - 1) * KF4 + tid);
            __syncthreads();

            float ig, fg, gg, og;
            if (layer0 && t == 0) {
                ig = g_pre0[u];
                fg = g_pre0[NH + u];
                gg = g_pre0[2 * NH + u];
                og = g_pre0[3 * NH + u];
            } else {
                float x0 = 0.f, x1 = 0.f, x2 = 0.f, x3 = 0.f;   // ih dots (quant units)
                float h0 = 0.f, h1 = 0.f, h2 = 0.f, h3 = 0.f;   // hh dots (quant units)
                if (haveX && haveH) {
                    #pragma unroll 2
                    for (int i = lane; i < KU4; i += 32) {
                        const float4 xlo = sx[2 * i], xhi = sx[2 * i + 1];
                        const float4 hlo = sh[2 * i], hhi = sh[2 * i + 1];
                        uint4 w;
                        w = __ldg(Wih4 + i);          ACC8(x0, w, xlo, xhi);
                        w = __ldg(Wih4 + GQ + i);     ACC8(x1, w, xlo, xhi);
                        w = __ldg(Wih4 + 2 * GQ + i); ACC8(x2, w, xlo, xhi);
                        w = __ldg(Wih4 + 3 * GQ + i); ACC8(x3, w, xlo, xhi);
                        w = __ldg(Whh4 + i);          ACC8(h0, w, hlo, hhi);
                        w = __ldg(Whh4 + GQ + i);     ACC8(h1, w, hlo, hhi);
                        w = __ldg(Whh4 + 2 * GQ + i); ACC8(h2, w, hlo, hhi);
                        w = __ldg(Whh4 + 3 * GQ + i); ACC8(h3, w, hlo, hhi);
                    }
                } else if (haveH) {   // layer 0, t>0: x == 0
                    #pragma unroll 2
                    for (int i = lane; i < KU4; i += 32) {
                        const float4 hlo = sh[2 * i], hhi = sh[2 * i + 1];
                        uint4 w;
                        w = __ldg(Whh4 + i);          ACC8(h0, w, hlo, hhi);
                        w = __ldg(Whh4 + GQ + i);     ACC8(h1, w, hlo, hhi);
                        w = __ldg(Whh4 + 2 * GQ + i); ACC8(h2, w, hlo, hhi);
                        w = __ldg(Whh4 + 3 * GQ + i); ACC8(h3, w, hlo, hhi);
                    }
                } else {              // l>0, t==0: h == 0
                    #pragma unroll 2
                    for (int i = lane; i < KU4; i += 32) {
                        const float4 xlo = sx[2 * i], xhi = sx[2 * i + 1];
                        uint4 w;
                        w = __ldg(Wih4 + i);          ACC8(x0, w, xlo, xhi);
                        w = __ldg(Wih4 + GQ + i);     ACC8(x1, w, xlo, xhi);
                        w = __ldg(Wih4 + 2 * GQ + i); ACC8(x2, w, xlo, xhi);
                        w = __ldg(Wih4 + 3 * GQ + i); ACC8(x3, w, xlo, xhi);
                    }
                }
                #pragma unroll
                for (int o = 16; o; o >>= 1) {
                    x0 += __shfl_xor_sync(0xffffffffu, x0, o);
                    x1 += __shfl_xor_sync(0xffffffffu, x1, o);
                    x2 += __shfl_xor_sync(0xffffffffu, x2, o);
                    x3 += __shfl_xor_sync(0xffffffffu, x3, o);
                    h0 += __shfl_xor_sync(0xffffffffu, h0, o);
                    h1 += __shfl_xor_sync(0xffffffffu, h1, o);
                    h2 += __shfl_xor_sync(0xffffffffu, h2, o);
                    h3 += __shfl_xor_sync(0xffffffffu, h3, o);
                }
                float si0 = 0.f, si1 = 0.f, si2 = 0.f, si3 = 0.f;
                if (haveX) {
                    si0 = sihs[u];          si1 = sihs[NH + u];
                    si2 = sihs[2 * NH + u]; si3 = sihs[3 * NH + u];
                }
                ig = x0 * si0 + h0 * shhs[u]          + bias[u];
                fg = x1 * si1 + h1 * shhs[NH + u]     + bias[NH + u];
                gg = x2 * si2 + h2 * shhs[2 * NH + u] + bias[2 * NH + u];
                og = x3 * si3 + h3 * shhs[3 * NH + u] + bias[3 * NH + u];
            }

            c = sigf(fg) * c + sigf(ig) * tanhf(gg);
            float h = sigf(og) * tanhf(c);
            if (lane == 0) out[(size_t)t * NH + u] = h;

            grid_barrier(sense);   // 1024 total (even parity: replay-safe)
        }
    }
}

// ---------------- epilogue: states[t] = h3[t] @ w_sp^T + b_sp ----------------
__global__ void proj_kernel(const float* __restrict__ wsp, const float* __restrict__ bsp,
                            float* __restrict__ out) {
    __shared__ float4 shh[KF4];
    const int t = blockIdx.x;
    const int tid = threadIdx.x;    // 256 threads
    const float4* h4 = (const float4*)g_hsB + (size_t)t * KF4;  // layer3 output in B
    shh[tid]       = h4[tid];
    shh[tid + 256] = h4[tid + 256];
    __syncthreads();
    const int widx = tid >> 5, lane = tid & 31;
    for (int o = widx; o < 64; o += 8) {
        const float4* wr = (const float4*)wsp + (size_t)o * KF4;
        float s = 0.f;
        #pragma unroll 4
        for (int i = lane; i < KF4; i += 32) {
            float4 w = __ldg(wr + i);
            float4 hv = shh[i];
            s += w.x * hv.x + w.y * hv.y + w.z * hv.z + w.w * hv.w;
        }
        #pragma unroll
        for (int off = 16; off; off >>= 1) s += __shfl_xor_sync(0xffffffffu, s, off);
        if (lane == 0) out[(size_t)t * 64 + o] = s + bsp[o];
    }
}

// ---------------- launch ----------------
extern "C" void kernel_launch(void* const* d_in, const int* in_sizes, int n_in,
                              void* d_out, int out_size) {
    const float* z      = (const float*)d_in[0];
    const float* w_ih0  = (const float*)d_in[1];
    const float* w_hh0  = (const float*)d_in[2];
    const float* b_ih0  = (const float*)d_in[3];
    const float* b_hh0  = (const float*)d_in[4];
    const float* w_ih_r = (const float*)d_in[5];
    const float* w_hh_r = (const float*)d_in[6];
    const float* b_ih_r = (const float*)d_in[7];
    const float* b_hh_r = (const float*)d_in[8];
    const float* w_sp   = (const float*)d_in[9];
    const float* b_sp   = (const float*)d_in[10];
    float* out = (float*)d_out;

    bias_kernel<<<64, 512>>>(b_ih0, b_hh0, b_ih_r, b_hh_r);
    quant_kernel<<<448, 512>>>(w_hh0, w_ih_r, w_hh_r);
    pre0_kernel<<<32, 256>>>(w_ih0, z);
    lstm_kernel<<<GRID, PBLOCK>>>();
    proj_kernel<<<TT, 256>>>(w_sp, b_sp, out);
}

// round 3
// speedup vs baseline: 1.4734x; 1.0046x over previous
#include <cuda_runtime.h>
#include <math.h>
#include <stdint.h>

// Problem constants
#define NZ   256
#define NH   2048
#define NG   8192      // 4*NH gate rows
#define TT   256       // timesteps
#define KF4  (NH/4)    // 512 float4 per h-vector
#define KU4  (NH/8)    // 256 uint4 (8 int16) per weight row
#define PBLOCK 512
#define PWARPS (PBLOCK/32)
#define GRID   (NH/PWARPS)   // 128 blocks: one warp per hidden unit

// ---------------- device scratch (no allocations allowed) ----------------
__device__ float g_bias[4][NG];          // b_ih + b_hh per layer
__device__ float g_pre0[NG];             // z @ W_ih0^T + b0 (layer0, t=0)
__device__ float g_hsA[TT * NH];         // ping-pong hidden-sequence buffers
__device__ float g_hsB[TT * NH];
__device__ unsigned g_count;             // grid barrier (returns to 0)
__device__ unsigned g_sense;             // parity; 1024 barriers (even) -> replay-safe

// quantized weights: biased uint16 (q = round(w/scale) + 32768)
__device__ unsigned short q_hh0[(size_t)NG * NH];       //  33.5 MB
__device__ unsigned short q_ihr[(size_t)3 * NG * NH];   // 100.7 MB
__device__ unsigned short q_hhr[(size_t)3 * NG * NH];   // 100.7 MB
__device__ float s_hh0[NG];              // per-row dequant scales
__device__ float s_ihr[3 * NG];
__device__ float s_hhr[3 * NG];

__device__ __forceinline__ float sigf(float x) { return 1.0f / (1.0f + expf(-x)); }

// biased-u16 -> float: PRMT builds 0x4B00'u16, FADD removes (2^23 + 32768)
#define CVT_LO(v) (__uint_as_float(__byte_perm((v), 0x4B000000u, 0x7410)) - 8421376.0f)
#define CVT_HI(v) (__uint_as_float(__byte_perm((v), 0x4B000000u, 0x7632)) - 8421376.0f)

// accumulate one uint4 (8 weights) against 8 h-values held in two float4s
#define ACC8(acc, w, lo, hi)                          \
    do {                                              \
        acc += CVT_LO((w).x) * (lo).x;                \
        acc += CVT_HI((w).x) * (lo).y;                \
        acc += CVT_LO((w).y) * (lo).z;                \
        acc += CVT_HI((w).y) * (lo).w;                \
        acc += CVT_LO((w).z) * (hi).x;                \
        acc += CVT_HI((w).z) * (hi).y;                \
        acc += CVT_LO((w).w) * (hi).z;                \
        acc += CVT_HI((w).w) * (hi).w;                \
    } while (0)

// ---------------- prologue: summed biases ----------------
__global__ void bias_kernel(const float* __restrict__ bi0, const float* __restrict__ bh0,
                            const float* __restrict__ bir, const float* __restrict__ bhr) {
    int idx = blockIdx.x * blockDim.x + threadIdx.x;   // 4*NG threads
    if (idx < 4 * NG) {
        int l = idx >> 13;
        int r = idx & (NG - 1);
        float v = (l == 0) ? (bi0[r] + bh0[r])
                           : (bir[(size_t)(l - 1) * NG + r] + bhr[(size_t)(l - 1) * NG + r]);
        g_bias[l][r] = v;
    }
}

// ---------------- prologue: quantize recurrent weights to biased u16 ----------------
// rows: [0,NG)       -> whh0
//       [NG,4NG)     -> wih_r (3 layers)
//       [4NG,7NG)    -> whh_r (3 layers)
__global__ void quant_kernel(const float* __restrict__ whh0,
                             const float* __restrict__ wihr,
                             const float* __restrict__ whhr) {
    int gw   = (blockIdx.x * blockDim.x + threadIdx.x) >> 5;
    int lane = threadIdx.x & 31;
    int nw   = (gridDim.x * blockDim.x) >> 5;
    for (int r = gw; r < 7 * NG; r += nw) {
        const float* src;
        unsigned short* dst;
        float* sc;
        if (r < NG) {
            src = whh0 + (size_t)r * NH; dst = q_hh0 + (size_t)r * NH; sc = &s_hh0[r];
        } else if (r < 4 * NG) {
            int rr = r - NG;
            src = wihr + (size_t)rr * NH; dst = q_ihr + (size_t)rr * NH; sc = &s_ihr[rr];
        } else {
            int rr = r - 4 * NG;
            src = whhr + (size_t)rr * NH; dst = q_hhr + (size_t)rr * NH; sc = &s_hhr[rr];
        }
        const float4* s4 = (const float4*)src;
        float m = 0.f;
        #pragma unroll 4
        for (int i = lane; i < KF4; i += 32) {
            float4 v = s4[i];
            m = fmaxf(m, fmaxf(fmaxf(fabsf(v.x), fabsf(v.y)), fmaxf(fabsf(v.z), fabsf(v.w))));
        }
        #pragma unroll
        for (int o = 16; o; o >>= 1) m = fmaxf(m, __shfl_xor_sync(0xffffffffu, m, o));
        float qs = (m > 0.f) ? 32767.0f / m : 0.f;
        if (lane == 0) *sc = (m > 0.f) ? m / 32767.0f : 0.f;
        ushort4* d4 = (ushort4*)dst;
        #pragma unroll 4
        for (int i = lane; i < KF4; i += 32) {
            float4 v = s4[i];   // L1 hit (row re-read)
            ushort4 o;
            o.x = (unsigned short)(__float2int_rn(v.x * qs) + 32768);
            o.y = (unsigned short)(__float2int_rn(v.y * qs) + 32768);
            o.z = (unsigned short)(__float2int_rn(v.z * qs) + 32768);
            o.w = (unsigned short)(__float2int_rn(v.w * qs) + 32768);
            d4[i] = o;
        }
    }
}

// ---------------- prologue: layer0 t=0 gates = z @ W_ih0^T + b0 (fp32) --------------
__global__ void pre0_kernel(const float* __restrict__ wih0, const float* __restrict__ z) {
    int gw   = (blockIdx.x * blockDim.x + threadIdx.x) >> 5;
    int lane = threadIdx.x & 31;
    int nw   = (gridDim.x * blockDim.x) >> 5;
    for (int row = gw; row < NG; row += nw) {
        const float* wr = wih0 + (size_t)row * NZ;
        float s = 0.f;
        for (int k = lane; k < NZ; k += 32) s += wr[k] * z[k];
        #pragma unroll
        for (int o = 16; o; o >>= 1) s += __shfl_xor_sync(0xffffffffu, s, o);
        if (lane == 0) g_pre0[row] = s + g_bias[0][row];
    }
}

// ---------------- grid-wide barrier ----------------
__device__ __forceinline__ void grid_barrier(unsigned& sense) {
    __syncthreads();
    if (threadIdx.x == 0) {
        unsigned s = sense ^ 1u;
        sense = s;
        __threadfence();
        if (atomicAdd(&g_count, 1u) == gridDim.x - 1u) {
            g_count = 0u;
            __threadfence();
            *((volatile unsigned*)&g_sense) = s;
        } else {
            while (*((volatile unsigned*)&g_sense) != s) { }
        }
        __threadfence();
    }
    __syncthreads();
}

// ---------------- main persistent LSTM kernel (int16 weights) ----------------
// 128 blocks x 512 threads: exactly one warp per hidden unit.
__global__ void __launch_bounds__(PBLOCK, 1)
lstm_kernel() {
    __shared__ float4 sx[KF4];   // x_t   (prev-layer hidden at step t)
    __shared__ float4 sh[KF4];   // h_{t-1} (this layer)

    const int tid  = threadIdx.x;
    const int lane = tid & 31;
    const int widx = tid >> 5;
    const int u    = blockIdx.x * PWARPS + widx;    // hidden unit, 0..2047
    const size_t GQ = (size_t)NH * KU4;             // uint4 stride between gate blocks

    unsigned sense = 0;

    for (int l = 0; l < 4; ++l) {
        const unsigned short* Wih = (l == 0) ? (const unsigned short*)0
                                             : q_ihr + (size_t)(l - 1) * NG * NH;
        const unsigned short* Whh = (l == 0) ? q_hh0
                                             : q_hhr + (size_t)(l - 1) * NG * NH;
        const float* sihs = (l == 0) ? (const float*)0 : s_ihr + (size_t)(l - 1) * NG;
        const float* shhs = (l == 0) ? s_hh0 : s_hhr + (size_t)(l - 1) * NG;
        const float* xs   = (l == 0) ? (const float*)0 : ((l & 1) ? g_hsA : g_hsB);
        float* out        = (l & 1) ? g_hsB : g_hsA;
        const float* bias = g_bias[l];
        const bool layer0 = (l == 0);

        const uint4* Wih4 = layer0 ? (const uint4*)0 : (const uint4*)Wih + (size_t)u * KU4;
        const uint4* Whh4 = (const uint4*)Whh + (size_t)u * KU4;

        float c = 0.f;   // register-resident cell state

        for (int t = 0; t < TT; ++t) {
            const bool haveX = (l > 0);
            const bool haveH = (t > 0);
            if (haveX) sx[tid] = __ldcg((const float4*)xs + (size_t)t * KF4 + tid);
            if (haveH) sh[tid] = __ldcg((const float4*)out + (size_t)(t - 1) * KF4 + tid);
            __syncthreads();

            float ig, fg, gg, og;
            if (layer0 && t == 0) {
                ig = g_pre0[u];
                fg = g_pre0[NH + u];
                gg = g_pre0[2 * NH + u];
                og = g_pre0[3 * NH + u];
            } else {
                float x0 = 0.f, x1 = 0.f, x2 = 0.f, x3 = 0.f;   // ih dots (quant units)
                float h0 = 0.f, h1 = 0.f, h2 = 0.f, h3 = 0.f;   // hh dots (quant units)
                if (haveX && haveH) {
                    #pragma unroll 2
                    for (int i = lane; i < KU4; i += 32) {
                        const float4 xlo = sx[2 * i], xhi = sx[2 * i + 1];
                        const float4 hlo = sh[2 * i], hhi = sh[2 * i + 1];
                        uint4 w;
                        w = __ldg(Wih4 + i);          ACC8(x0, w, xlo, xhi);
                        w = __ldg(Wih4 + GQ + i);     ACC8(x1, w, xlo, xhi);
                        w = __ldg(Wih4 + 2 * GQ + i); ACC8(x2, w, xlo, xhi);
                        w = __ldg(Wih4 + 3 * GQ + i); ACC8(x3, w, xlo, xhi);
                        w = __ldg(Whh4 + i);          ACC8(h0, w, hlo, hhi);
                        w = __ldg(Whh4 + GQ + i);     ACC8(h1, w, hlo, hhi);
                        w = __ldg(Whh4 + 2 * GQ + i); ACC8(h2, w, hlo, hhi);
                        w = __ldg(Whh4 + 3 * GQ + i); ACC8(h3, w, hlo, hhi);
                    }
                } else if (haveH) {   // layer 0, t>0: x == 0
                    #pragma unroll 2
                    for (int i = lane; i < KU4; i += 32) {
                        const float4 hlo = sh[2 * i], hhi = sh[2 * i + 1];
                        uint4 w;
                        w = __ldg(Whh4 + i);          ACC8(h0, w, hlo, hhi);
                        w = __ldg(Whh4 + GQ + i);     ACC8(h1, w, hlo, hhi);
                        w = __ldg(Whh4 + 2 * GQ + i); ACC8(h2, w, hlo, hhi);
                        w = __ldg(Whh4 + 3 * GQ + i); ACC8(h3, w, hlo, hhi);
                    }
                } else {              // l>0, t==0: h == 0
                    #pragma unroll 2
                    for (int i = lane; i < KU4; i += 32) {
                        const float4 xlo = sx[2 * i], xhi = sx[2 * i + 1];
                        uint4 w;
                        w = __ldg(Wih4 + i);          ACC8(x0, w, xlo, xhi);
                        w = __ldg(Wih4 + GQ + i);     ACC8(x1, w, xlo, xhi);
                        w = __ldg(Wih4 + 2 * GQ + i); ACC8(x2, w, xlo, xhi);
                        w = __ldg(Wih4 + 3 * GQ + i); ACC8(x3, w, xlo, xhi);
                    }
                }
                #pragma unroll
                for (int o = 16; o; o >>= 1) {
                    x0 += __shfl_xor_sync(0xffffffffu, x0, o);
                    x1 += __shfl_xor_sync(0xffffffffu, x1, o);
                    x2 += __shfl_xor_sync(0xffffffffu, x2, o);
                    x3 += __shfl_xor_sync(0xffffffffu, x3, o);
                    h0 += __shfl_xor_sync(0xffffffffu, h0, o);
                    h1 += __shfl_xor_sync(0xffffffffu, h1, o);
                    h2 += __shfl_xor_sync(0xffffffffu, h2, o);
                    h3 += __shfl_xor_sync(0xffffffffu, h3, o);
                }
                float si0 = 0.f, si1 = 0.f, si2 = 0.f, si3 = 0.f;
                if (haveX) {
                    si0 = sihs[u];          si1 = sihs[NH + u];
                    si2 = sihs[2 * NH + u]; si3 = sihs[3 * NH + u];
                }
                ig = x0 * si0 + h0 * shhs[u]          + bias[u];
                fg = x1 * si1 + h1 * shhs[NH + u]     + bias[NH + u];
                gg = x2 * si2 + h2 * shhs[2 * NH + u] + bias[2 * NH + u];
                og = x3 * si3 + h3 * shhs[3 * NH + u] + bias[3 * NH + u];
            }

            c = sigf(fg) * c + sigf(ig) * tanhf(gg);
            float h = sigf(og) * tanhf(c);
            if (lane == 0) out[(size_t)t * NH + u] = h;

            grid_barrier(sense);   // 1024 total (even parity: replay-safe)
        }
    }
}

// ---------------- epilogue: states[t] = h3[t] @ w_sp^T + b_sp ----------------
__global__ void proj_kernel(const float* __restrict__ wsp, const float* __restrict__ bsp,
                            float* __restrict__ out) {
    __shared__ float4 shh[KF4];
    const int t = blockIdx.x;
    const int tid = threadIdx.x;    // 256 threads
    const float4* h4 = (const float4*)g_hsB + (size_t)t * KF4;  // layer3 output in B
    shh[tid]       = h4[tid];
    shh[tid + 256] = h4[tid + 256];
    __syncthreads();
    const int widx = tid >> 5, lane = tid & 31;
    for (int o = widx; o < 64; o += 8) {
        const float4* wr = (const float4*)wsp + (size_t)o * KF4;
        float s = 0.f;
        #pragma unroll 4
        for (int i = lane; i < KF4; i += 32) {
            float4 w = __ldg(wr + i);
            float4 hv = shh[i];
            s += w.x * hv.x + w.y * hv.y + w.z * hv.z + w.w * hv.w;
        }
        #pragma unroll
        for (int off = 16; off; off >>= 1) s += __shfl_xor_sync(0xffffffffu, s, off);
        if (lane == 0) out[(size_t)t * 64 + o] = s + bsp[o];
    }
}

// ---------------- launch ----------------
extern "C" void kernel_launch(void* const* d_in, const int* in_sizes, int n_in,
                              void* d_out, int out_size) {
    const float* z      = (const float*)d_in[0];
    const float* w_ih0  = (const float*)d_in[1];
    const float* w_hh0  = (const float*)d_in[2];
    const float* b_ih0  = (const float*)d_in[3];
    const float* b_hh0  = (const float*)d_in[4];
    const float* w_ih_r = (const float*)d_in[5];
    const float* w_hh_r = (const float*)d_in[6];
    const float* b_ih_r = (const float*)d_in[7];
    const float* b_hh_r = (const float*)d_in[8];
    const float* w_sp   = (const float*)d_in[9];
    const float* b_sp   = (const float*)d_in[10];
    float* out = (float*)d_out;

    bias_kernel<<<64, 512>>>(b_ih0, b_hh0, b_ih_r, b_hh_r);
    quant_kernel<<<448, 512>>>(w_hh0, w_ih_r, w_hh_r);
    pre0_kernel<<<32, 256>>>(w_ih0, z);
    lstm_kernel<<<GRID, PBLOCK>>>();
    proj_kernel<<<TT, 256>>>(w_sp, b_sp, out);
}